// round 6
// baseline (speedup 1.0000x reference)
#include <cuda_runtime.h>

#define NN 20000
#define NE 100000
#define NG 64
#define FF 128

// ---------------- device scratch (no allocations allowed) ----------------
__device__ float g_bufA[NN * 512];   // layer1 aggregated x (4 channels x 128)
__device__ float g_bufB[NN * 512];   // h1 = relu(agg @ W1c + b1c), channel-chunked
__device__ float g_bufC[NN * 256];   // t2 = h1 @ W2
__device__ float g_bufD[NN * 256];   // h2 = relu(agg(t2) + b2)
__device__ float g_bufE[NN * 128];   // t3 = h2 @ W3
__device__ float g_bufF[NN * 128];   // h3 = agg(t3) + b3
__device__ float4 g_dis4[NN];        // holds deg (init 1.0) then rsqrt(deg) per channel
__device__ float  g_disN[NN];        // rsqrt(indeg+1)
__device__ int    g_indeg[NN];
__device__ int    g_cursor[NN];
__device__ int    g_rowptr[NN + 1];
__device__ int    g_src[NE];         // CSR: source node per slot (grouped by target)
__device__ float4 g_nrm4[NE];        // per-edge norm, 4 channels
__device__ float  g_nrmN[NE];        // per-edge norm, unit weights
__device__ int    g_gcnt[NG];
__device__ int    g_gptr[NG + 1];
__device__ float  g_pool[2 * NG * 256]; // [tower][graph][mean128|max128]

// ---------------- degree / CSR construction ----------------

__global__ void k_init_deg() {
    int v = blockIdx.x * blockDim.x + threadIdx.x;
    if (v < NN) g_dis4[v] = make_float4(1.f, 1.f, 1.f, 1.f);  // self-loop weight
}

__global__ void k_edge_deg(const int* __restrict__ ei, const float4* __restrict__ ea) {
    int e = blockIdx.x * blockDim.x + threadIdx.x;
    if (e >= NE) return;
    int v = ei[NE + e];                 // col = target
    float4 a = ea[e];
    float* d = reinterpret_cast<float*>(g_dis4) + (size_t)v * 4;
    atomicAdd(d + 0, a.x);
    atomicAdd(d + 1, a.y);
    atomicAdd(d + 2, a.z);
    atomicAdd(d + 3, a.w);
    atomicAdd(&g_indeg[v], 1);
}

__global__ void k_dis() {
    int v = blockIdx.x * blockDim.x + threadIdx.x;
    if (v >= NN) return;
    float4 d = g_dis4[v];
    g_dis4[v] = make_float4(rsqrtf(d.x), rsqrtf(d.y), rsqrtf(d.z), rsqrtf(d.w));
    g_disN[v] = rsqrtf((float)g_indeg[v] + 1.0f);
}

__global__ void k_scan20k() {   // single block, 256 threads: exclusive scan of g_indeg -> g_rowptr
    __shared__ int sh[256];
    int tid = threadIdx.x;
    const int per = (NN + 255) / 256;
    int start = tid * per;
    int s = 0;
    for (int i = 0; i < per; i++) {
        int idx = start + i;
        if (idx < NN) s += g_indeg[idx];
    }
    sh[tid] = s;
    __syncthreads();
    for (int off = 1; off < 256; off <<= 1) {
        int v = (tid >= off) ? sh[tid - off] : 0;
        __syncthreads();
        sh[tid] += v;
        __syncthreads();
    }
    int run = (tid == 0) ? 0 : sh[tid - 1];
    for (int i = 0; i < per; i++) {
        int idx = start + i;
        if (idx < NN) {
            g_rowptr[idx] = run;
            run += g_indeg[idx];
        }
    }
    if (tid == 255) g_rowptr[NN] = run;
}

__global__ void k_fill(const int* __restrict__ ei, const float4* __restrict__ ea) {
    int e = blockIdx.x * blockDim.x + threadIdx.x;
    if (e >= NE) return;
    int u = ei[e];          // source
    int v = ei[NE + e];     // target
    int p = g_rowptr[v] + atomicAdd(&g_cursor[v], 1);
    g_src[p] = u;
    float4 a = ea[e];
    float4 du = g_dis4[u];
    float4 dv = g_dis4[v];
    g_nrm4[p] = make_float4(du.x * a.x * dv.x, du.y * a.y * dv.y,
                            du.z * a.z * dv.z, du.w * a.w * dv.w);
    g_nrmN[p] = g_disN[u] * g_disN[v];
}

// ---------------- aggregation (gather, no atomics) ----------------

// Layer1: aggregate x once for all 4 channels. Output channel-chunked [N,512].
__global__ void k_agg1(const float* __restrict__ x) {
    int v = blockIdx.x;
    int f = threadIdx.x;      // 128
    float4 dv = g_dis4[v];
    float xv = x[(size_t)v * FF + f];
    float a0 = dv.x * dv.x * xv;   // self loop: dis_c[v]*1*dis_c[v]
    float a1 = dv.y * dv.y * xv;
    float a2 = dv.z * dv.z * xv;
    float a3 = dv.w * dv.w * xv;
    int s = g_rowptr[v], e = g_rowptr[v + 1];
    for (int p = s; p < e; ++p) {
        int u = g_src[p];
        float4 nm = g_nrm4[p];
        float xu = __ldg(&x[(size_t)u * FF + f]);
        a0 = fmaf(nm.x, xu, a0);
        a1 = fmaf(nm.y, xu, a1);
        a2 = fmaf(nm.z, xu, a2);
        a3 = fmaf(nm.w, xu, a3);
    }
    float* out = g_bufA + (size_t)v * 512;
    out[f]        = a0;
    out[128 + f]  = a1;
    out[256 + f]  = a2;
    out[384 + f]  = a3;
}

// Layers 2/3: aggregate t (F = blockDim.x), add bias, optional relu.
__global__ void k_aggN(const float* __restrict__ t, float* __restrict__ out,
                       const float* __restrict__ bias, int do_relu) {
    int v = blockIdx.x;
    int f = threadIdx.x;
    int F = blockDim.x;
    float dn = g_disN[v];
    float acc = dn * dn * t[(size_t)v * F + f];
    int s = g_rowptr[v], e = g_rowptr[v + 1];
    for (int p = s; p < e; ++p) {
        acc = fmaf(g_nrmN[p], __ldg(&t[(size_t)g_src[p] * F + f]), acc);
    }
    acc += bias[f];
    if (do_relu) acc = fmaxf(acc, 0.f);
    out[(size_t)v * F + f] = acc;
}

// ---------------- SGEMM: C[M,N] = A[M,K](lda) @ W[K,N] (+bias, relu) ----------------
// 128x128 block tile, BK=16, 256 threads, 8x8 per thread.
__global__ void __launch_bounds__(256, 2)
k_sgemm(const float* __restrict__ A, const float* __restrict__ W,
        float* __restrict__ C, const float* __restrict__ bias,
        int M, int N, int K, int lda, int ldc, int do_relu) {
    const int BM = 128, BN = 128, BK = 16;
    __shared__ float As[BK][BM + 4];
    __shared__ float Bs[BK][BN];
    int tid = threadIdx.x;
    int brow = blockIdx.y, bcol = blockIdx.x;
    int tx = tid & 15, ty = tid >> 4;

    float acc[8][8];
#pragma unroll
    for (int i = 0; i < 8; i++)
#pragma unroll
        for (int j = 0; j < 8; j++) acc[i][j] = 0.f;

    int arow0 = tid >> 2;            // 0..63
    int acol4 = (tid & 3) * 4;       // 0,4,8,12
    int wrow0 = tid >> 5;            // 0..7
    int wcol4 = (tid & 31) * 4;      // 0..124

    for (int k0 = 0; k0 < K; k0 += BK) {
#pragma unroll
        for (int i = 0; i < 2; i++) {
            int r = arow0 + i * 64;
            int gr = brow * BM + r;
            if (gr >= M) gr = M - 1;   // clamp; stores are guarded
            float4 v = *reinterpret_cast<const float4*>(A + (size_t)gr * lda + k0 + acol4);
            As[acol4 + 0][r] = v.x;
            As[acol4 + 1][r] = v.y;
            As[acol4 + 2][r] = v.z;
            As[acol4 + 3][r] = v.w;
        }
#pragma unroll
        for (int i = 0; i < 2; i++) {
            int kr = wrow0 + i * 8;
            float4 v = *reinterpret_cast<const float4*>(W + (size_t)(k0 + kr) * N + bcol * BN + wcol4);
            *reinterpret_cast<float4*>(&Bs[kr][wcol4]) = v;
        }
        __syncthreads();
#pragma unroll
        for (int kk = 0; kk < BK; kk++) {
            float ra[8], rb[8];
#pragma unroll
            for (int i = 0; i < 8; i++) ra[i] = As[kk][ty * 8 + i];
#pragma unroll
            for (int j = 0; j < 8; j++) rb[j] = Bs[kk][tx * 8 + j];
#pragma unroll
            for (int i = 0; i < 8; i++)
#pragma unroll
                for (int j = 0; j < 8; j++) acc[i][j] = fmaf(ra[i], rb[j], acc[i][j]);
        }
        __syncthreads();
    }

#pragma unroll
    for (int i = 0; i < 8; i++) {
        int gr = brow * BM + ty * 8 + i;
        if (gr < M) {
#pragma unroll
            for (int j = 0; j < 8; j++) {
                int gc = bcol * BN + tx * 8 + j;
                float v = acc[i][j];
                if (bias) v += __ldg(&bias[gc]);
                if (do_relu) v = fmaxf(v, 0.f);
                C[(size_t)gr * ldc + gc] = v;
            }
        }
    }
}

// ---------------- pooling ----------------

__global__ void k_hist(const int* __restrict__ batch) {
    int i = blockIdx.x * blockDim.x + threadIdx.x;
    if (i < NN) atomicAdd(&g_gcnt[batch[i]], 1);
}

__global__ void k_scan64() {   // 64 threads
    __shared__ int sh[NG];
    int t = threadIdx.x;
    sh[t] = g_gcnt[t];
    __syncthreads();
    for (int off = 1; off < NG; off <<= 1) {
        int v = (t >= off) ? sh[t - off] : 0;
        __syncthreads();
        sh[t] += v;
        __syncthreads();
    }
    g_gptr[t + 1] = sh[t];
    if (t == 0) g_gptr[0] = 0;
}

__global__ void k_pool(const float* __restrict__ h, float* __restrict__ pout) {
    int g = blockIdx.x;
    int f = threadIdx.x;  // 128
    int s = g_gptr[g], e = g_gptr[g + 1];
    float sum = 0.f, mx = -3.4e38f;
    for (int v = s; v < e; ++v) {
        float x = h[(size_t)v * 128 + f];
        sum += x;
        mx = fmaxf(mx, x);
    }
    int cnt = e - s;
    float mean = sum / (float)(cnt > 0 ? cnt : 1);
    pout[g * 256 + f]       = mean;
    pout[g * 256 + 128 + f] = (cnt > 0) ? mx : 0.f;
}

// ---------------- final MLP ----------------

__global__ void k_mlp(const float* __restrict__ p0, const float* __restrict__ p1,
                      const float* __restrict__ Wm1, const float* __restrict__ bm1,
                      const float* __restrict__ Wm2, const float* __restrict__ bm2,
                      float* __restrict__ out) {
    int g = blockIdx.x;
    int t = threadIdx.x;  // 128
    __shared__ float h[512];
    __shared__ float z[8];
    for (int i = t; i < 256; i += 128) {
        h[i]       = p0[g * 256 + i];
        h[256 + i] = p1[g * 256 + i];
    }
    __syncthreads();
    if (t < 8) {
        float s = bm1[t];
        for (int i = 0; i < 512; i++) s = fmaf(h[i], Wm1[i * 8 + t], s);
        z[t] = fmaxf(s, 0.f);
    }
    __syncthreads();
    if (t < 2) {
        float s = bm2[t];
        for (int j = 0; j < 8; j++) s = fmaf(z[j], Wm2[j * 2 + t], s);
        out[g * 2 + t] = s;
    }
}

// ---------------- host orchestration ----------------

extern "C" void kernel_launch(void* const* d_in, const int* in_sizes, int n_in,
                              void* d_out, int out_size) {
    (void)in_sizes; (void)n_in; (void)out_size;

    void* p;
    float *bufA, *bufB, *bufC, *bufD, *bufE, *bufF, *poolp;
    int *indeg, *cursor, *gcnt;
    cudaGetSymbolAddress(&p, g_bufA);  bufA  = (float*)p;
    cudaGetSymbolAddress(&p, g_bufB);  bufB  = (float*)p;
    cudaGetSymbolAddress(&p, g_bufC);  bufC  = (float*)p;
    cudaGetSymbolAddress(&p, g_bufD);  bufD  = (float*)p;
    cudaGetSymbolAddress(&p, g_bufE);  bufE  = (float*)p;
    cudaGetSymbolAddress(&p, g_bufF);  bufF  = (float*)p;
    cudaGetSymbolAddress(&p, g_pool);  poolp = (float*)p;
    cudaGetSymbolAddress(&p, g_indeg); indeg = (int*)p;
    cudaGetSymbolAddress(&p, g_cursor); cursor = (int*)p;
    cudaGetSymbolAddress(&p, g_gcnt);  gcnt  = (int*)p;

    const float* W1[4] = {(const float*)d_in[8],  (const float*)d_in[10],
                          (const float*)d_in[12], (const float*)d_in[14]};
    const float* b1[4] = {(const float*)d_in[9],  (const float*)d_in[11],
                          (const float*)d_in[13], (const float*)d_in[15]};
    const float* W2  = (const float*)d_in[16];
    const float* b2  = (const float*)d_in[17];
    const float* W3  = (const float*)d_in[18];
    const float* b3  = (const float*)d_in[19];
    const float* Wm1 = (const float*)d_in[20];
    const float* bm1 = (const float*)d_in[21];
    const float* Wm2 = (const float*)d_in[22];
    const float* bm2 = (const float*)d_in[23];

    const int M = NN;
    const dim3 g157_1(1, (M + 127) / 128);
    const dim3 g157_2(2, (M + 127) / 128);
    const int GN = (NN + 255) / 256;
    const int GE = (NE + 255) / 256;

    for (int tw = 0; tw < 2; tw++) {
        const float*  x     = (const float*)d_in[tw ? 3 : 0];
        const float4* ea    = (const float4*)d_in[tw ? 4 : 1];
        const int*    ei    = (const int*)d_in[tw ? 5 : 2];
        const int*    batch = (const int*)d_in[tw ? 7 : 6];

        cudaMemsetAsync(indeg, 0, NN * sizeof(int));
        cudaMemsetAsync(cursor, 0, NN * sizeof(int));
        cudaMemsetAsync(gcnt, 0, NG * sizeof(int));

        k_init_deg<<<GN, 256>>>();
        k_edge_deg<<<GE, 256>>>(ei, ea);
        k_dis<<<GN, 256>>>();
        k_scan20k<<<1, 256>>>();
        k_fill<<<GE, 256>>>(ei, ea);

        // Layer 1: aggregate x (all 4 channels), then 4 GEMMs [N,128]@[128,128] +bias +relu
        k_agg1<<<NN, 128>>>(x);
        for (int c = 0; c < 4; c++) {
            k_sgemm<<<g157_1, 256>>>(bufA + c * 128, W1[c], bufB + c * 128, b1[c],
                                     M, 128, 128, 512, 512, 1);
        }

        // Layer 2: t2 = h1 @ W2 [N,512]->[N,256]; then aggregate + b2 + relu
        k_sgemm<<<g157_2, 256>>>(bufB, W2, bufC, nullptr, M, 256, 512, 512, 256, 0);
        k_aggN<<<NN, 256>>>(bufC, bufD, b2, 1);

        // Layer 3: t3 = h2 @ W3 [N,256]->[N,128]; then aggregate + b3 (no relu)
        k_sgemm<<<g157_1, 256>>>(bufD, W3, bufE, nullptr, M, 128, 256, 256, 128, 0);
        k_aggN<<<NN, 128>>>(bufE, bufF, b3, 0);

        // Pool
        k_hist<<<GN, 256>>>(batch);
        k_scan64<<<1, 64>>>();
        k_pool<<<NG, 128>>>(bufF, poolp + tw * NG * 256);
    }

    k_mlp<<<NG, 128>>>(poolp, poolp + NG * 256, Wm1, bm1, Wm2, bm2, (float*)d_out);
}

// round 7
// speedup vs baseline: 1.0037x; 1.0037x over previous
#include <cuda_runtime.h>

#define NN 20000
#define NE 100000
#define NG 64
#define FF 128

// ---------------- device scratch (no allocations allowed) ----------------
__device__ float g_bufA[NN * 512];   // layer1 aggregated x (4 channels x 128)
__device__ float g_bufB[NN * 512];   // h1 = relu(agg @ W1c + b1c), channel-chunked
__device__ float g_bufC[NN * 256];   // t2 = h1 @ W2
__device__ float g_bufD[NN * 256];   // h2 = relu(agg(t2) + b2)
__device__ float g_bufE[NN * 128];   // t3 = h2 @ W3
__device__ float g_bufF[NN * 128];   // h3 = agg(t3) + b3
__device__ float4 g_dis4[NN];        // holds deg (init 1.0) then rsqrt(deg) per channel
__device__ float  g_disN[NN];        // rsqrt(indeg+1)
__device__ int    g_indeg[NN];
__device__ int    g_cursor[NN];
__device__ int    g_rowptr[NN + 1];
__device__ int    g_src[NE];         // CSR: source node per slot (grouped by target)
__device__ float4 g_nrm4[NE];        // per-edge norm, 4 channels
__device__ float  g_nrmN[NE];        // per-edge norm, unit weights
__device__ int    g_gcnt[NG];
__device__ int    g_gptr[NG + 1];
__device__ float  g_pool[2 * NG * 256]; // [tower][graph][mean128|max128]

// ---------------- degree / CSR construction ----------------

__global__ void k_init_deg() {
    int v = blockIdx.x * blockDim.x + threadIdx.x;
    if (v < NN) g_dis4[v] = make_float4(1.f, 1.f, 1.f, 1.f);  // self-loop weight
}

__global__ void k_edge_deg(const int* __restrict__ ei, const float4* __restrict__ ea) {
    int e = blockIdx.x * blockDim.x + threadIdx.x;
    if (e >= NE) return;
    int v = ei[NE + e];                 // col = target
    float4 a = ea[e];
    float* d = reinterpret_cast<float*>(g_dis4) + (size_t)v * 4;
    atomicAdd(d + 0, a.x);
    atomicAdd(d + 1, a.y);
    atomicAdd(d + 2, a.z);
    atomicAdd(d + 3, a.w);
    atomicAdd(&g_indeg[v], 1);
}

__global__ void k_dis() {
    int v = blockIdx.x * blockDim.x + threadIdx.x;
    if (v >= NN) return;
    float4 d = g_dis4[v];
    g_dis4[v] = make_float4(rsqrtf(d.x), rsqrtf(d.y), rsqrtf(d.z), rsqrtf(d.w));
    g_disN[v] = rsqrtf((float)g_indeg[v] + 1.0f);
}

__global__ void k_scan20k() {   // single block, 256 threads: exclusive scan of g_indeg -> g_rowptr
    __shared__ int sh[256];
    int tid = threadIdx.x;
    const int per = (NN + 255) / 256;
    int start = tid * per;
    int s = 0;
    for (int i = 0; i < per; i++) {
        int idx = start + i;
        if (idx < NN) s += g_indeg[idx];
    }
    sh[tid] = s;
    __syncthreads();
    for (int off = 1; off < 256; off <<= 1) {
        int v = (tid >= off) ? sh[tid - off] : 0;
        __syncthreads();
        sh[tid] += v;
        __syncthreads();
    }
    int run = (tid == 0) ? 0 : sh[tid - 1];
    for (int i = 0; i < per; i++) {
        int idx = start + i;
        if (idx < NN) {
            g_rowptr[idx] = run;
            run += g_indeg[idx];
        }
    }
    if (tid == 255) g_rowptr[NN] = run;
}

__global__ void k_fill(const int* __restrict__ ei, const float4* __restrict__ ea) {
    int e = blockIdx.x * blockDim.x + threadIdx.x;
    if (e >= NE) return;
    int u = ei[e];          // source
    int v = ei[NE + e];     // target
    int p = g_rowptr[v] + atomicAdd(&g_cursor[v], 1);
    g_src[p] = u;
    float4 a = ea[e];
    float4 du = g_dis4[u];
    float4 dv = g_dis4[v];
    g_nrm4[p] = make_float4(du.x * a.x * dv.x, du.y * a.y * dv.y,
                            du.z * a.z * dv.z, du.w * a.w * dv.w);
    g_nrmN[p] = g_disN[u] * g_disN[v];
}

// ---------------- aggregation (gather, no atomics) ----------------

// Layer1: aggregate x once for all 4 channels. Output channel-chunked [N,512].
__global__ void k_agg1(const float* __restrict__ x) {
    int v = blockIdx.x;
    int f = threadIdx.x;      // 128
    float4 dv = g_dis4[v];
    float xv = x[(size_t)v * FF + f];
    float a0 = dv.x * dv.x * xv;   // self loop: dis_c[v]*1*dis_c[v]
    float a1 = dv.y * dv.y * xv;
    float a2 = dv.z * dv.z * xv;
    float a3 = dv.w * dv.w * xv;
    int s = g_rowptr[v], e = g_rowptr[v + 1];
    for (int p = s; p < e; ++p) {
        int u = g_src[p];
        float4 nm = g_nrm4[p];
        float xu = __ldg(&x[(size_t)u * FF + f]);
        a0 = fmaf(nm.x, xu, a0);
        a1 = fmaf(nm.y, xu, a1);
        a2 = fmaf(nm.z, xu, a2);
        a3 = fmaf(nm.w, xu, a3);
    }
    float* out = g_bufA + (size_t)v * 512;
    out[f]        = a0;
    out[128 + f]  = a1;
    out[256 + f]  = a2;
    out[384 + f]  = a3;
}

// Layers 2/3: aggregate t (F = blockDim.x), add bias, optional relu.
__global__ void k_aggN(const float* __restrict__ t, float* __restrict__ out,
                       const float* __restrict__ bias, int do_relu) {
    int v = blockIdx.x;
    int f = threadIdx.x;
    int F = blockDim.x;
    float dn = g_disN[v];
    float acc = dn * dn * t[(size_t)v * F + f];
    int s = g_rowptr[v], e = g_rowptr[v + 1];
    for (int p = s; p < e; ++p) {
        acc = fmaf(g_nrmN[p], __ldg(&t[(size_t)g_src[p] * F + f]), acc);
    }
    acc += bias[f];
    if (do_relu) acc = fmaxf(acc, 0.f);
    out[(size_t)v * F + f] = acc;
}

// ---------------- SGEMM: C[M,N] = A[M,K](lda) @ W[K,N] (+bias, relu) ----------------
// 128x128 block tile, BK=16, 256 threads, 8x8 per thread.
__global__ void __launch_bounds__(256, 2)
k_sgemm(const float* __restrict__ A, const float* __restrict__ W,
        float* __restrict__ C, const float* __restrict__ bias,
        int M, int N, int K, int lda, int ldc, int do_relu) {
    const int BM = 128, BN = 128, BK = 16;
    __shared__ float As[BK][BM + 4];
    __shared__ float Bs[BK][BN];
    int tid = threadIdx.x;
    int brow = blockIdx.y, bcol = blockIdx.x;
    int tx = tid & 15, ty = tid >> 4;

    float acc[8][8];
#pragma unroll
    for (int i = 0; i < 8; i++)
#pragma unroll
        for (int j = 0; j < 8; j++) acc[i][j] = 0.f;

    int arow0 = tid >> 2;            // 0..63
    int acol4 = (tid & 3) * 4;       // 0,4,8,12
    int wrow0 = tid >> 5;            // 0..7
    int wcol4 = (tid & 31) * 4;      // 0..124

    for (int k0 = 0; k0 < K; k0 += BK) {
#pragma unroll
        for (int i = 0; i < 2; i++) {
            int r = arow0 + i * 64;
            int gr = brow * BM + r;
            if (gr >= M) gr = M - 1;   // clamp; stores are guarded
            float4 v = *reinterpret_cast<const float4*>(A + (size_t)gr * lda + k0 + acol4);
            As[acol4 + 0][r] = v.x;
            As[acol4 + 1][r] = v.y;
            As[acol4 + 2][r] = v.z;
            As[acol4 + 3][r] = v.w;
        }
#pragma unroll
        for (int i = 0; i < 2; i++) {
            int kr = wrow0 + i * 8;
            float4 v = *reinterpret_cast<const float4*>(W + (size_t)(k0 + kr) * N + bcol * BN + wcol4);
            *reinterpret_cast<float4*>(&Bs[kr][wcol4]) = v;
        }
        __syncthreads();
#pragma unroll
        for (int kk = 0; kk < BK; kk++) {
            float ra[8], rb[8];
#pragma unroll
            for (int i = 0; i < 8; i++) ra[i] = As[kk][ty * 8 + i];
#pragma unroll
            for (int j = 0; j < 8; j++) rb[j] = Bs[kk][tx * 8 + j];
#pragma unroll
            for (int i = 0; i < 8; i++)
#pragma unroll
                for (int j = 0; j < 8; j++) acc[i][j] = fmaf(ra[i], rb[j], acc[i][j]);
        }
        __syncthreads();
    }

#pragma unroll
    for (int i = 0; i < 8; i++) {
        int gr = brow * BM + ty * 8 + i;
        if (gr < M) {
#pragma unroll
            for (int j = 0; j < 8; j++) {
                int gc = bcol * BN + tx * 8 + j;
                float v = acc[i][j];
                if (bias) v += __ldg(&bias[gc]);
                if (do_relu) v = fmaxf(v, 0.f);
                C[(size_t)gr * ldc + gc] = v;
            }
        }
    }
}

// ---------------- pooling ----------------

__global__ void k_hist(const int* __restrict__ batch) {
    int i = blockIdx.x * blockDim.x + threadIdx.x;
    if (i < NN) atomicAdd(&g_gcnt[batch[i]], 1);
}

__global__ void k_scan64() {   // 64 threads
    __shared__ int sh[NG];
    int t = threadIdx.x;
    sh[t] = g_gcnt[t];
    __syncthreads();
    for (int off = 1; off < NG; off <<= 1) {
        int v = (t >= off) ? sh[t - off] : 0;
        __syncthreads();
        sh[t] += v;
        __syncthreads();
    }
    g_gptr[t + 1] = sh[t];
    if (t == 0) g_gptr[0] = 0;
}

__global__ void k_pool(const float* __restrict__ h, float* __restrict__ pout) {
    int g = blockIdx.x;
    int f = threadIdx.x;  // 128
    int s = g_gptr[g], e = g_gptr[g + 1];
    float sum = 0.f, mx = -3.4e38f;
    for (int v = s; v < e; ++v) {
        float x = h[(size_t)v * 128 + f];
        sum += x;
        mx = fmaxf(mx, x);
    }
    int cnt = e - s;
    float mean = sum / (float)(cnt > 0 ? cnt : 1);
    pout[g * 256 + f]       = mean;
    pout[g * 256 + 128 + f] = (cnt > 0) ? mx : 0.f;
}

// ---------------- final MLP ----------------

__global__ void k_mlp(const float* __restrict__ p0, const float* __restrict__ p1,
                      const float* __restrict__ Wm1, const float* __restrict__ bm1,
                      const float* __restrict__ Wm2, const float* __restrict__ bm2,
                      float* __restrict__ out) {
    int g = blockIdx.x;
    int t = threadIdx.x;  // 128
    __shared__ float h[512];
    __shared__ float z[8];
    for (int i = t; i < 256; i += 128) {
        h[i]       = p0[g * 256 + i];
        h[256 + i] = p1[g * 256 + i];
    }
    __syncthreads();
    if (t < 8) {
        float s = bm1[t];
        for (int i = 0; i < 512; i++) s = fmaf(h[i], Wm1[i * 8 + t], s);
        z[t] = fmaxf(s, 0.f);
    }
    __syncthreads();
    if (t < 2) {
        float s = bm2[t];
        for (int j = 0; j < 8; j++) s = fmaf(z[j], Wm2[j * 2 + t], s);
        out[g * 2 + t] = s;
    }
}

// ---------------- host orchestration ----------------

extern "C" void kernel_launch(void* const* d_in, const int* in_sizes, int n_in,
                              void* d_out, int out_size) {
    (void)in_sizes; (void)n_in; (void)out_size;

    void* p;
    float *bufA, *bufB, *bufC, *bufD, *bufE, *bufF, *poolp;
    int *indeg, *cursor, *gcnt;
    cudaGetSymbolAddress(&p, g_bufA);  bufA  = (float*)p;
    cudaGetSymbolAddress(&p, g_bufB);  bufB  = (float*)p;
    cudaGetSymbolAddress(&p, g_bufC);  bufC  = (float*)p;
    cudaGetSymbolAddress(&p, g_bufD);  bufD  = (float*)p;
    cudaGetSymbolAddress(&p, g_bufE);  bufE  = (float*)p;
    cudaGetSymbolAddress(&p, g_bufF);  bufF  = (float*)p;
    cudaGetSymbolAddress(&p, g_pool);  poolp = (float*)p;
    cudaGetSymbolAddress(&p, g_indeg); indeg = (int*)p;
    cudaGetSymbolAddress(&p, g_cursor); cursor = (int*)p;
    cudaGetSymbolAddress(&p, g_gcnt);  gcnt  = (int*)p;

    const float* W1[4] = {(const float*)d_in[8],  (const float*)d_in[10],
                          (const float*)d_in[12], (const float*)d_in[14]};
    const float* b1[4] = {(const float*)d_in[9],  (const float*)d_in[11],
                          (const float*)d_in[13], (const float*)d_in[15]};
    const float* W2  = (const float*)d_in[16];
    const float* b2  = (const float*)d_in[17];
    const float* W3  = (const float*)d_in[18];
    const float* b3  = (const float*)d_in[19];
    const float* Wm1 = (const float*)d_in[20];
    const float* bm1 = (const float*)d_in[21];
    const float* Wm2 = (const float*)d_in[22];
    const float* bm2 = (const float*)d_in[23];

    const int M = NN;
    const dim3 g157_1(1, (M + 127) / 128);
    const dim3 g157_2(2, (M + 127) / 128);
    const int GN = (NN + 255) / 256;
    const int GE = (NE + 255) / 256;

    for (int tw = 0; tw < 2; tw++) {
        const float*  x     = (const float*)d_in[tw ? 3 : 0];
        const float4* ea    = (const float4*)d_in[tw ? 4 : 1];
        const int*    ei    = (const int*)d_in[tw ? 5 : 2];
        const int*    batch = (const int*)d_in[tw ? 7 : 6];

        cudaMemsetAsync(indeg, 0, NN * sizeof(int));
        cudaMemsetAsync(cursor, 0, NN * sizeof(int));
        cudaMemsetAsync(gcnt, 0, NG * sizeof(int));

        k_init_deg<<<GN, 256>>>();
        k_edge_deg<<<GE, 256>>>(ei, ea);
        k_dis<<<GN, 256>>>();
        k_scan20k<<<1, 256>>>();
        k_fill<<<GE, 256>>>(ei, ea);

        // Layer 1: aggregate x (all 4 channels), then 4 GEMMs [N,128]@[128,128] +bias +relu
        k_agg1<<<NN, 128>>>(x);
        for (int c = 0; c < 4; c++) {
            k_sgemm<<<g157_1, 256>>>(bufA + c * 128, W1[c], bufB + c * 128, b1[c],
                                     M, 128, 128, 512, 512, 1);
        }

        // Layer 2: t2 = h1 @ W2 [N,512]->[N,256]; then aggregate + b2 + relu
        k_sgemm<<<g157_2, 256>>>(bufB, W2, bufC, nullptr, M, 256, 512, 512, 256, 0);
        k_aggN<<<NN, 256>>>(bufC, bufD, b2, 1);

        // Layer 3: t3 = h2 @ W3 [N,256]->[N,128]; then aggregate + b3 (no relu)
        k_sgemm<<<g157_1, 256>>>(bufD, W3, bufE, nullptr, M, 128, 256, 256, 128, 0);
        k_aggN<<<NN, 128>>>(bufE, bufF, b3, 0);

        // Pool
        k_hist<<<GN, 256>>>(batch);
        k_scan64<<<1, 64>>>();
        k_pool<<<NG, 128>>>(bufF, poolp + tw * NG * 256);
    }

    k_mlp<<<NG, 128>>>(poolp, poolp + NG * 256, Wm1, bm1, Wm2, bm2, (float*)d_out);
}